// round 5
// baseline (speedup 1.0000x reference)
#include <cuda_runtime.h>
#include <cuda_bf16.h>
#include <math.h>

#define SEQ   2048
#define NH    16
#define DQK   576
#define DV    512
#define NTOP  1024
#define SCALE 0.08838834764831845f

typedef unsigned long long u64;

__device__ __align__(16) float g_q    [SEQ * NH * DQK];
__device__ __align__(16) float g_kv   [SEQ * DQK];
__device__ __align__(16) float g_ql   [SEQ * NH * 128];
__device__ __align__(16) float g_iq   [SEQ * NH * 128];
__device__ __align__(16) float g_ik   [SEQ * 128];
__device__ __align__(16) float g_w    [SEQ * NH];
__device__ __align__(16) float g_part [8 * SEQ * 128];
__device__ __align__(16) float g_partw[8 * SEQ * 16];
__device__ __align__(16) int   g_sel  [SEQ * NTOP];
__device__               int   g_nsel [SEQ];
__device__ __align__(16) float g_attn [SEQ * NH * DV];

// ---- packed f32x2 helpers (sm_103a) ----
__device__ __forceinline__ u64 pk2(float lo, float hi) {
    u64 r; asm("mov.b64 %0,{%1,%2};" : "=l"(r) : "f"(lo), "f"(hi)); return r;
}
__device__ __forceinline__ u64 pkdup(float x) { return pk2(x, x); }
__device__ __forceinline__ void upk(u64 v, float& lo, float& hi) {
    asm("mov.b64 {%0,%1},%2;" : "=f"(lo), "=f"(hi) : "l"(v));
}
__device__ __forceinline__ u64 fma2(u64 a, u64 b, u64 c) {
    u64 d; asm("fma.rn.f32x2 %0,%1,%2,%3;" : "=l"(d) : "l"(a), "l"(b), "l"(c)); return d;
}
__device__ __forceinline__ u64 mul2(u64 a, u64 b) {
    u64 d; asm("mul.rn.f32x2 %0,%1,%2;" : "=l"(d) : "l"(a), "l"(b)); return d;
}
__device__ __forceinline__ float hsum2(u64 v) { float l, h; upk(v, l, h); return l + h; }

// ---- generic SGEMM core: C[m,n]=sum_k A[m,k]*B[n,k] (or B[k,n] if transB) ----
__device__ __forceinline__
void gemm_core(const float* __restrict__ A, const float* __restrict__ B,
               float* __restrict__ C, int N, int K, int lda, int ldb, int ldc,
               int bm, int bn, int transB)
{
    __shared__ float As[8][128], Bs[8][128];
    const int tid = threadIdx.x;
    const int arow = tid >> 1, acol = (tid & 1) << 2;
    const int bkk = tid >> 5, bnc = (tid & 31) << 2;
    const int tm = (tid >> 4) << 3, tn = (tid & 15) << 3;
    u64 acc[8][4];
#pragma unroll
    for (int i = 0; i < 8; i++)
#pragma unroll
        for (int p = 0; p < 4; p++) acc[i][p] = 0ULL;

    for (int k0 = 0; k0 < K; k0 += 8) {
        float4 av = *(const float4*)(A + (bm + arow) * lda + k0 + acol);
        As[acol+0][arow]=av.x; As[acol+1][arow]=av.y; As[acol+2][arow]=av.z; As[acol+3][arow]=av.w;
        if (!transB) {
            float4 bv = make_float4(0.f,0.f,0.f,0.f);
            if (bn + arow < N) bv = *(const float4*)(B + (bn + arow) * ldb + k0 + acol);
            Bs[acol+0][arow]=bv.x; Bs[acol+1][arow]=bv.y; Bs[acol+2][arow]=bv.z; Bs[acol+3][arow]=bv.w;
        } else {
            float4 bv = make_float4(0.f,0.f,0.f,0.f);
            if (bn + bnc < N) bv = *(const float4*)(B + (k0 + bkk) * ldb + bn + bnc);
            *(float4*)&Bs[bkk][bnc] = bv;
        }
        __syncthreads();
#pragma unroll
        for (int kk = 0; kk < 8; kk++) {
            float4 a0=*(const float4*)&As[kk][tm], a1=*(const float4*)&As[kk][tm+4];
            const u64* bp = (const u64*)&Bs[kk][tn];
            u64 b0=bp[0], b1=bp[1], b2=bp[2], b3=bp[3];
            float aarr[8] = {a0.x,a0.y,a0.z,a0.w,a1.x,a1.y,a1.z,a1.w};
#pragma unroll
            for (int i = 0; i < 8; i++) {
                u64 ai = pkdup(aarr[i]);
                acc[i][0]=fma2(ai,b0,acc[i][0]); acc[i][1]=fma2(ai,b1,acc[i][1]);
                acc[i][2]=fma2(ai,b2,acc[i][2]); acc[i][3]=fma2(ai,b3,acc[i][3]);
            }
        }
        __syncthreads();
    }
#pragma unroll
    for (int i = 0; i < 8; i++) {
        int row = bm + tm + i;
        float c[8];
#pragma unroll
        for (int p = 0; p < 4; p++) upk(acc[i][p], c[2*p], c[2*p+1]);
#pragma unroll
        for (int j = 0; j < 8; j++) {
            int col = bn + tn + j;
            if (col < N) C[row * ldc + col] = c[j];
        }
    }
}

__global__ __launch_bounds__(256, 2)
void sgemm_nt(const float* __restrict__ A, const float* __restrict__ B,
              float* __restrict__ C, int N, int K, int lda, int ldb, int ldc,
              long long sA, long long sB, long long sC, int transB)
{
    gemm_core(A + (long long)blockIdx.z * sA, B + (long long)blockIdx.z * sB,
              C + (long long)blockIdx.z * sC, N, K, lda, ldb, ldc,
              blockIdx.y * 128, blockIdx.x * 128, transB);
}

// fused ckv+w split-K GEMM: z<8 -> ckv chunk z ; z>=8 -> w chunk z-8
__global__ __launch_bounds__(256, 2)
void sgemm_cw(const float* __restrict__ hidden, const float* __restrict__ wkw,
              const float* __restrict__ wpw)
{
    int z = blockIdx.z;
    if (z < 8) {
        gemm_core(hidden + z*256, wkw + z*256, g_part + (long long)z*SEQ*128,
                  128, 256, 2048, 2048, 128, blockIdx.y*128, 0, 0);
    } else {
        int zz = z - 8;
        gemm_core(hidden + zz*256, wpw + zz*256, g_partw + (long long)zz*SEQ*16,
                  16, 256, 2048, 2048, 16, blockIdx.y*128, 0, 0);
    }
}

// fused: reduce w, reduce ckv -> ik (rmsnorm+rope), build kv, qrot, rope_iq
__global__ __launch_bounds__(256)
void fused_build(const float* __restrict__ kp, const float* __restrict__ kr,
                 const float* __restrict__ qr, const float* __restrict__ cosb,
                 const float* __restrict__ sinb, const float* __restrict__ knorm,
                 const float* __restrict__ wpb)
{
    const int s = blockIdx.x, t = threadIdx.x;
    __shared__ float ckv_s[128];
    __shared__ float red[2];
    __shared__ float s_inv;
    if (t < 128) {
        float v = 0.f;
#pragma unroll
        for (int z = 0; z < 8; z++) v += g_part[z*(SEQ*128) + s*128 + t];
        ckv_s[t] = v;
    } else if (t < 144) {
        int i = t - 128;
        float v = 0.f;
#pragma unroll
        for (int z = 0; z < 8; z++) v += g_partw[z*(SEQ*16) + s*16 + i];
        g_w[s*16 + i] = fabsf(v + wpb[i]);
    }
    __syncthreads();
    if (t < 64) {
        float pv = ckv_s[64 + t];
        float ss = pv * pv;
#pragma unroll
        for (int o = 16; o; o >>= 1) ss += __shfl_xor_sync(0xffffffffu, ss, o);
        if ((t & 31) == 0) red[t >> 5] = ss;
    }
    __syncthreads();
    if (t == 0) s_inv = rsqrtf((red[0] + red[1]) * (1.f/64.f) + 1e-6f);
    __syncthreads();
    if (t < 64) g_ik[s*128 + 64 + t] = ckv_s[64 + t] * s_inv * knorm[t];
    else if (t < 96) {
        int i = t - 64;
        float x0 = ckv_s[2*i], x1 = ckv_s[2*i + 1];
        g_ik[s*128 + i]      = x0*cosb[s*64 + i]      - x1*sinb[s*64 + i];
        g_ik[s*128 + 32 + i] = x1*cosb[s*64 + 32 + i] + x0*sinb[s*64 + 32 + i];
    }
    for (int idx = t; idx < 576; idx += 256)
        g_kv[s*576 + idx] = (idx < 512) ? kp[s*512 + idx] : kr[s*64 + idx - 512];
    for (int idx = t; idx < 1024; idx += 256) {
        int h = idx >> 6, i = idx & 63;
        g_q[s*9216 + h*576 + 512 + i] = qr[(h*2048 + s)*64 + i];
    }
    for (int idx = t; idx < 512; idx += 256) {
        int h = idx >> 5, i = idx & 31;
        int base = s*2048 + h*128;
        float x0 = g_ql[base + 2*i], x1 = g_ql[base + 2*i + 1];
        g_iq[base + i]      = x0*cosb[s*64 + i]      - x1*sinb[s*64 + i];
        g_iq[base + 32 + i] = x1*cosb[s*64 + 32 + i] + x0*sinb[s*64 + 32 + i];
        g_iq[base + 64 + i] = g_ql[base + 64 + i];
        g_iq[base + 96 + i] = g_ql[base + 96 + i];
    }
}

// scores + exact top-1024 (ties -> lowest index, matching jax.lax.top_k)
__global__ __launch_bounds__(256)
void indexer_kernel()
{
    const int qi = blockIdx.x, t = threadIdx.x;
    if (qi < NTOP) {
        for (int k = t; k <= qi; k += 256) g_sel[qi*NTOP + k] = k;
        if (t == 0) g_nsel[qi] = qi + 1;
        return;
    }
    __shared__ float4 iq4[16*33];
    __shared__ float4 ik4[32*33];
    __shared__ float  ssc[SEQ];
    __shared__ float  wsh[16];
    __shared__ unsigned int hist[256];
    __shared__ unsigned long long s_prefix;
    __shared__ unsigned int s_kneed, s_cnt;

    const float4* iqg = (const float4*)g_iq + qi * 512;
#pragma unroll
    for (int u = 0; u < 2; u++) {
        int f = t + 256*u;
        iq4[(f >> 5)*33 + (f & 31)] = iqg[f];
    }
    if (t < 16) wsh[t] = g_w[qi*16 + t];
    if (t == 0) { s_prefix = 0ULL; s_kneed = NTOP; s_cnt = 0; }
    __syncthreads();

    const int n = qi + 1;
    const int row = t >> 3, cb = t & 7;
    for (int k0 = 0; k0 < n; k0 += 32) {
        int k = k0 + row;
        float4* dst = &ik4[row*33];
        if (k < n) {
            const float4* src = (const float4*)g_ik + k*32;
#pragma unroll
            for (int u = 0; u < 4; u++) dst[cb + 8*u] = src[cb + 8*u];
        } else {
            float4 z = make_float4(0.f,0.f,0.f,0.f);
#pragma unroll
            for (int u = 0; u < 4; u++) dst[cb + 8*u] = z;
        }
        __syncthreads();
        const u64* ap0 = (const u64*)&iq4[(cb*2)*33];
        const u64* ap1 = (const u64*)&iq4[(cb*2 + 1)*33];
        const u64* bp  = (const u64*)&ik4[row*33];
        u64 a0a=0ULL, a0b=0ULL, a1a=0ULL, a1b=0ULL;
#pragma unroll
        for (int dc = 0; dc < 32; dc++) {
            u64 b0 = bp[2*dc], b1 = bp[2*dc+1];
            a0a = fma2(ap0[2*dc],   b0, a0a);
            a0b = fma2(ap0[2*dc+1], b1, a0b);
            a1a = fma2(ap1[2*dc],   b0, a1a);
            a1b = fma2(ap1[2*dc+1], b1, a1b);
        }
        float a0 = hsum2(a0a) + hsum2(a0b);
        float a1 = hsum2(a1a) + hsum2(a1b);
        float part = wsh[cb*2]*fmaxf(a0*SCALE, 0.f) + wsh[cb*2+1]*fmaxf(a1*SCALE, 0.f);
        part += __shfl_xor_sync(0xffffffffu, part, 1);
        part += __shfl_xor_sync(0xffffffffu, part, 2);
        part += __shfl_xor_sync(0xffffffffu, part, 4);
        if (cb == 0 && k < n) ssc[k] = part;
        __syncthreads();
    }

    for (int pass = 5; pass >= 0; pass--) {
        const int shift = pass * 8;
        hist[t] = 0u;
        __syncthreads();
        unsigned long long pref = s_prefix;
        for (int k = t; k < n; k += 256) {
            unsigned long long key =
                (((unsigned long long)__float_as_uint(ssc[k])) << 11) | (unsigned)(2047 - k);
            if ((key >> (shift + 8)) == (pref >> (shift + 8)))
                atomicAdd(&hist[(unsigned)(key >> shift) & 255u], 1u);
        }
        __syncthreads();
        if (t == 0) {
            unsigned c = 0;
            for (int d = 255; d >= 0; d--) {
                unsigned c2 = c + hist[d];
                if (c2 >= s_kneed) {
                    s_prefix |= ((unsigned long long)d) << shift;
                    s_kneed  -= c;
                    break;
                }
                c = c2;
            }
        }
        __syncthreads();
    }
    const unsigned long long T = s_prefix;
    for (int k = t; k < n; k += 256) {
        unsigned long long key =
            (((unsigned long long)__float_as_uint(ssc[k])) << 11) | (unsigned)(2047 - k);
        if (key >= T) g_sel[qi*NTOP + atomicAdd(&s_cnt, 1u)] = k;
    }
    if (t == 0) g_nsel[qi] = NTOP;
}

// ============================================================================
// attn v2: per-query CTA, 64-key tiles, GEMM-style register blocking.
// score: thread=(hg:4 heads, dh:144-dim quarter, kg) computes 4hx4k partials.
// softmax: one warp-reduce per head per tile.  P@V: thread=(hg, dg:8 dims).
// ============================================================================
#define TK 64
#define SW 578
#define ASMEM ((TK*SW + 16*SW + 4160 + 1024 + 48) * 4)

__global__ __launch_bounds__(256, 1)
void attn_kernel2()
{
    extern __shared__ float sm[];
    float* kvs  = sm;                  // TK x SW
    float* qs   = kvs + TK*SW;         // 16 x SW
    float* sred = qs + 16*SW;          // 4*16 rows x 65
    float* Sp   = sred + 4160;         // 16 x 64
    float* mS   = Sp + 1024;
    float* lS   = mS + 16;
    float* fS   = lS + 16;

    const int qi = blockIdx.x, t = threadIdx.x;
    const int hg = t >> 6;             // 4 heads: hg*4..+3
    const int dh = (t >> 4) & 3;       // 144-dim quarter
    const int kg = t & 15;             // key group (keys kg+16j)
    const int dg = t & 63;             // O-phase dim group

    for (int i = t; i < 16*576; i += 256) {
        int h = i / 576, d = i - h*576;
        qs[h*SW + d] = g_q[qi*9216 + i] * SCALE;
    }
    if (t < 16) { mS[t] = -INFINITY; lS[t] = 0.f; }

    u64 O[4][4];
#pragma unroll
    for (int i = 0; i < 4; i++)
#pragma unroll
        for (int u = 0; u < 4; u++) O[i][u] = 0ULL;

    const int n = g_nsel[qi];
    const int* lst = g_sel + qi*NTOP;
    const float2* kv2 = (const float2*)g_kv;
    __syncthreads();

    for (int base = 0; base < n; base += TK) {
        const int tk = min(TK, n - base);
        // gather tile (float2, padded rows)
        for (int i = t; i < TK*288; i += 256) {
            int r = i / 288, c = i - r*288;
            float2 v = make_float2(0.f, 0.f);
            if (r < tk) v = kv2[(long long)__ldg(&lst[base + r]) * 288 + c];
            *(float2*)&kvs[r*SW + c*2] = v;
        }
        __syncthreads();

        // score partials: 4h x 4k over 144 dims
        {
            u64 acc[4][4];
#pragma unroll
            for (int i = 0; i < 4; i++)
#pragma unroll
                for (int j = 0; j < 4; j++) acc[i][j] = 0ULL;
            const float* qb = qs + (hg*4)*SW + dh*144;
            const float* bb = kvs + kg*SW + dh*144;
#pragma unroll 4
            for (int dc = 0; dc < 72; dc++) {
                u64 qv[4], bv[4];
#pragma unroll
                for (int i = 0; i < 4; i++) qv[i] = *(const u64*)(qb + i*SW + 2*dc);
#pragma unroll
                for (int j = 0; j < 4; j++) bv[j] = *(const u64*)(bb + j*16*SW + 2*dc);
#pragma unroll
                for (int i = 0; i < 4; i++)
#pragma unroll
                    for (int j = 0; j < 4; j++) acc[i][j] = fma2(qv[i], bv[j], acc[i][j]);
            }
#pragma unroll
            for (int i = 0; i < 4; i++)
#pragma unroll
                for (int j = 0; j < 4; j++)
                    sred[(dh*16 + hg*4 + i)*65 + kg + 16*j] = hsum2(acc[i][j]);
        }
        __syncthreads();

        // reduce dim quarters + mask
        for (int idx = t; idx < 1024; idx += 256) {
            int h = idx >> 6, k = idx & 63;
            float s = sred[h*65 + k] + sred[(16+h)*65 + k]
                    + sred[(32+h)*65 + k] + sred[(48+h)*65 + k];
            Sp[idx] = (k < tk) ? s : -INFINITY;
        }
        __syncthreads();

        // online softmax: warp w -> heads 2w, 2w+1
        {
            int w = t >> 5, lane = t & 31;
#pragma unroll
            for (int hh = 0; hh < 2; hh++) {
                int h = w*2 + hh;
                float s0 = Sp[h*64 + lane], s1 = Sp[h*64 + 32 + lane];
                float mx = fmaxf(s0, s1);
#pragma unroll
                for (int o = 16; o; o >>= 1) mx = fmaxf(mx, __shfl_xor_sync(0xffffffffu, mx, o));
                float mo = mS[h];
                float nm = fmaxf(mo, mx);
                float p0 = __expf(s0 - nm), p1 = __expf(s1 - nm);
                Sp[h*64 + lane] = p0; Sp[h*64 + 32 + lane] = p1;
                float ps = p0 + p1;
#pragma unroll
                for (int o = 16; o; o >>= 1) ps += __shfl_xor_sync(0xffffffffu, ps, o);
                if (lane == 0) {
                    float fv = __expf(mo - nm);
                    lS[h] = lS[h]*fv + ps;
                    mS[h] = nm; fS[h] = fv;
                }
            }
        }
        __syncthreads();

        // rescale O + accumulate P@V (dims 2dg+128u)
        {
#pragma unroll
            for (int i = 0; i < 4; i++) {
                u64 f2 = pkdup(fS[hg*4 + i]);
#pragma unroll
                for (int u = 0; u < 4; u++) O[i][u] = mul2(O[i][u], f2);
            }
            const float* vb = kvs + 2*dg;
            for (int k = 0; k < tk; k++) {
                u64 pv[4];
#pragma unroll
                for (int i = 0; i < 4; i++) pv[i] = pkdup(Sp[(hg*4 + i)*64 + k]);
                const float* vr = vb + k*SW;
                u64 b0 = *(const u64*)vr,        b1 = *(const u64*)(vr + 128);
                u64 b2 = *(const u64*)(vr + 256), b3 = *(const u64*)(vr + 384);
#pragma unroll
                for (int i = 0; i < 4; i++) {
                    O[i][0] = fma2(pv[i], b0, O[i][0]);
                    O[i][1] = fma2(pv[i], b1, O[i][1]);
                    O[i][2] = fma2(pv[i], b2, O[i][2]);
                    O[i][3] = fma2(pv[i], b3, O[i][3]);
                }
            }
        }
        __syncthreads();
    }

#pragma unroll
    for (int i = 0; i < 4; i++) {
        u64 inv2 = pkdup(1.f / lS[hg*4 + i]);
#pragma unroll
        for (int u = 0; u < 4; u++) {
            u64 r = mul2(O[i][u], inv2);
            float2 v; upk(r, v.x, v.y);
            *(float2*)&g_attn[qi*8192 + (hg*4 + i)*512 + 2*dg + 128*u] = v;
        }
    }
}

template <typename T> static T* sym(const void* s) {
    void* p = nullptr; cudaGetSymbolAddress(&p, s); return (T*)p;
}

extern "C" void kernel_launch(void* const* d_in, const int* in_sizes, int n_in,
                              void* d_out, int out_size)
{
    (void)in_sizes; (void)n_in; (void)out_size;
    const float* q_latent = (const float*)d_in[0];
    const float* hidden   = (const float*)d_in[1];
    const float* cosb     = (const float*)d_in[2];
    const float* sinb     = (const float*)d_in[3];
    const float* q_pass   = (const float*)d_in[4];
    const float* q_rot    = (const float*)d_in[5];
    const float* k_pass   = (const float*)d_in[6];
    const float* k_rot    = (const float*)d_in[7];
    const float* kvb      = (const float*)d_in[9];
    const float* wqb      = (const float*)d_in[10];
    const float* wkw      = (const float*)d_in[11];
    const float* knorm    = (const float*)d_in[12];
    const float* wpw      = (const float*)d_in[13];
    const float* wpb      = (const float*)d_in[14];
    float* out = (float*)d_out;

    float* p_q    = sym<float>(g_q);
    float* p_ql   = sym<float>(g_ql);
    float* p_attn = sym<float>(g_attn);

    cudaFuncSetAttribute(attn_kernel2, cudaFuncAttributeMaxDynamicSharedMemorySize, ASMEM);

    // 1: ql = q_latent @ wq_b^T   (2048x2048, K=1536)
    sgemm_nt<<<dim3(16,16,1), 256>>>(q_latent, wqb, p_ql, 2048, 1536,
                                     1536, 1536, 2048, 0, 0, 0, 0);
    // 2: fused ckv + w split-K partials
    sgemm_cw<<<dim3(1,16,16), 256>>>(hidden, wkw, wpw);
    // 3: q_abs[h]: q_pass[h] @ k_b[h]^T (NN via transB)
    sgemm_nt<<<dim3(4,16,16), 256>>>(q_pass, kvb, p_q, 512, 128,
                                     128, 512, NH*DQK,
                                     (long long)SEQ*128, 256LL*512, DQK, 1);
    // 4: fused reductions + builds + ropes
    fused_build<<<SEQ, 256>>>(k_pass, k_rot, q_rot, cosb, sinb, knorm, wpb);
    // 5: indexer scores + exact top-1024
    indexer_kernel<<<SEQ, 256>>>();
    // 6: sparse attention (profiled launch)
    attn_kernel2<<<SEQ, 256, ASMEM>>>();
    // 7: out[s,h,d] = sum_r attn[s,h,r] * v_b[h,d,r]
    sgemm_nt<<<dim3(1,16,16), 256>>>(p_attn, kvb + 128*512, out, 128, 512,
                                     NH*DV, 512, NH*128,
                                     512LL, 256LL*512, 128LL, 0);
}

// round 6
// speedup vs baseline: 1.0805x; 1.0805x over previous
#include <cuda_runtime.h>
#include <cuda_bf16.h>
#include <math.h>

#define SEQ   2048
#define NH    16
#define DQK   576
#define DV    512
#define NTOP  1024
#define SCALE 0.08838834764831845f

typedef unsigned long long u64;

__device__ __align__(16) float g_q    [SEQ * NH * DQK];
__device__ __align__(16) float g_kv   [SEQ * DQK];
__device__ __align__(16) float g_ql   [SEQ * NH * 128];
__device__ __align__(16) float g_iq   [SEQ * NH * 128];
__device__ __align__(16) float g_ik   [SEQ * 128];
__device__ __align__(16) float g_w    [SEQ * NH];
__device__ __align__(16) float g_part [8 * SEQ * 128];
__device__ __align__(16) float g_partw[8 * SEQ * 16];
__device__ __align__(16) int   g_sel  [SEQ * NTOP];
__device__               int   g_nsel [SEQ];
__device__ __align__(16) float g_attn [SEQ * NH * DV];

// ---- packed f32x2 helpers (sm_103a) ----
__device__ __forceinline__ u64 pk2(float lo, float hi) {
    u64 r; asm("mov.b64 %0,{%1,%2};" : "=l"(r) : "f"(lo), "f"(hi)); return r;
}
__device__ __forceinline__ u64 pkdup(float x) { return pk2(x, x); }
__device__ __forceinline__ void upk(u64 v, float& lo, float& hi) {
    asm("mov.b64 {%0,%1},%2;" : "=f"(lo), "=f"(hi) : "l"(v));
}
__device__ __forceinline__ u64 fma2(u64 a, u64 b, u64 c) {
    u64 d; asm("fma.rn.f32x2 %0,%1,%2,%3;" : "=l"(d) : "l"(a), "l"(b), "l"(c)); return d;
}
__device__ __forceinline__ u64 mul2(u64 a, u64 b) {
    u64 d; asm("mul.rn.f32x2 %0,%1,%2;" : "=l"(d) : "l"(a), "l"(b)); return d;
}
__device__ __forceinline__ float hsum2(u64 v) { float l, h; upk(v, l, h); return l + h; }

// ---- generic SGEMM core: C[m,n]=sum_k A[m,k]*B[n,k] (or B[k,n] if transB) ----
__device__ __forceinline__
void gemm_core(const float* __restrict__ A, const float* __restrict__ B,
               float* __restrict__ C, int N, int K, int lda, int ldb, int ldc,
               int bm, int bn, int transB)
{
    __shared__ float As[8][128], Bs[8][128];
    const int tid = threadIdx.x;
    const int arow = tid >> 1, acol = (tid & 1) << 2;
    const int bkk = tid >> 5, bnc = (tid & 31) << 2;
    const int tm = (tid >> 4) << 3, tn = (tid & 15) << 3;
    u64 acc[8][4];
#pragma unroll
    for (int i = 0; i < 8; i++)
#pragma unroll
        for (int p = 0; p < 4; p++) acc[i][p] = 0ULL;

    for (int k0 = 0; k0 < K; k0 += 8) {
        float4 av = *(const float4*)(A + (bm + arow) * lda + k0 + acol);
        As[acol+0][arow]=av.x; As[acol+1][arow]=av.y; As[acol+2][arow]=av.z; As[acol+3][arow]=av.w;
        if (!transB) {
            float4 bv = make_float4(0.f,0.f,0.f,0.f);
            if (bn + arow < N) bv = *(const float4*)(B + (bn + arow) * ldb + k0 + acol);
            Bs[acol+0][arow]=bv.x; Bs[acol+1][arow]=bv.y; Bs[acol+2][arow]=bv.z; Bs[acol+3][arow]=bv.w;
        } else {
            float4 bv = make_float4(0.f,0.f,0.f,0.f);
            if (bn + bnc < N) bv = *(const float4*)(B + (k0 + bkk) * ldb + bn + bnc);
            *(float4*)&Bs[bkk][bnc] = bv;
        }
        __syncthreads();
#pragma unroll
        for (int kk = 0; kk < 8; kk++) {
            float4 a0=*(const float4*)&As[kk][tm], a1=*(const float4*)&As[kk][tm+4];
            const u64* bp = (const u64*)&Bs[kk][tn];
            u64 b0=bp[0], b1=bp[1], b2=bp[2], b3=bp[3];
            float aarr[8] = {a0.x,a0.y,a0.z,a0.w,a1.x,a1.y,a1.z,a1.w};
#pragma unroll
            for (int i = 0; i < 8; i++) {
                u64 ai = pkdup(aarr[i]);
                acc[i][0]=fma2(ai,b0,acc[i][0]); acc[i][1]=fma2(ai,b1,acc[i][1]);
                acc[i][2]=fma2(ai,b2,acc[i][2]); acc[i][3]=fma2(ai,b3,acc[i][3]);
            }
        }
        __syncthreads();
    }
#pragma unroll
    for (int i = 0; i < 8; i++) {
        int row = bm + tm + i;
        float c[8];
#pragma unroll
        for (int p = 0; p < 4; p++) upk(acc[i][p], c[2*p], c[2*p+1]);
#pragma unroll
        for (int j = 0; j < 8; j++) {
            int col = bn + tn + j;
            if (col < N) C[row * ldc + col] = c[j];
        }
    }
}

// mega-GEMM: ql (256 blocks) + ckv/w split-K (256) + q_abs (1024) in one launch
__global__ __launch_bounds__(256, 2)
void sgemm_all(const float* __restrict__ q_latent, const float* __restrict__ wqb,
               const float* __restrict__ hidden,   const float* __restrict__ wkw,
               const float* __restrict__ wpw,      const float* __restrict__ q_pass,
               const float* __restrict__ kvb)
{
    const int bid = blockIdx.x;
    if (bid < 256) {
        gemm_core(q_latent, wqb, g_ql, 2048, 1536, 1536, 1536, 2048,
                  (bid >> 4) * 128, (bid & 15) * 128, 0);
    } else if (bid < 512) {
        int i = bid - 256, z = i >> 4, by = i & 15;
        if (z < 8)
            gemm_core(hidden + z*256, wkw + z*256, g_part + (long long)z*SEQ*128,
                      128, 256, 2048, 2048, 128, by*128, 0, 0);
        else
            gemm_core(hidden + (z-8)*256, wpw + (z-8)*256, g_partw + (long long)(z-8)*SEQ*16,
                      16, 256, 2048, 2048, 16, by*128, 0, 0);
    } else {
        int i = bid - 512, bx = i & 3, by = (i >> 2) & 15, h = i >> 6;
        gemm_core(q_pass + (long long)h*SEQ*128, kvb + (long long)h*256*512,
                  g_q + h*576, 512, 128, 128, 512, NH*DQK, by*128, bx*128, 1);
    }
}

__global__ __launch_bounds__(256, 2)
void sgemm_nt(const float* __restrict__ A, const float* __restrict__ B,
              float* __restrict__ C, int N, int K, int lda, int ldb, int ldc,
              long long sA, long long sB, long long sC, int transB)
{
    gemm_core(A + (long long)blockIdx.z * sA, B + (long long)blockIdx.z * sB,
              C + (long long)blockIdx.z * sC, N, K, lda, ldb, ldc,
              blockIdx.y * 128, blockIdx.x * 128, transB);
}

// fused: reduce w, reduce ckv -> ik (rmsnorm+rope), build kv, qrot, rope_iq
__global__ __launch_bounds__(256)
void fused_build(const float* __restrict__ kp, const float* __restrict__ kr,
                 const float* __restrict__ qr, const float* __restrict__ cosb,
                 const float* __restrict__ sinb, const float* __restrict__ knorm,
                 const float* __restrict__ wpb)
{
    const int s = blockIdx.x, t = threadIdx.x;
    __shared__ float ckv_s[128];
    __shared__ float red[2];
    __shared__ float s_inv;
    if (t < 128) {
        float v = 0.f;
#pragma unroll
        for (int z = 0; z < 8; z++) v += g_part[z*(SEQ*128) + s*128 + t];
        ckv_s[t] = v;
    } else if (t < 144) {
        int i = t - 128;
        float v = 0.f;
#pragma unroll
        for (int z = 0; z < 8; z++) v += g_partw[z*(SEQ*16) + s*16 + i];
        g_w[s*16 + i] = fabsf(v + wpb[i]);
    }
    __syncthreads();
    if (t < 64) {
        float pv = ckv_s[64 + t];
        float ss = pv * pv;
#pragma unroll
        for (int o = 16; o; o >>= 1) ss += __shfl_xor_sync(0xffffffffu, ss, o);
        if ((t & 31) == 0) red[t >> 5] = ss;
    }
    __syncthreads();
    if (t == 0) s_inv = rsqrtf((red[0] + red[1]) * (1.f/64.f) + 1e-6f);
    __syncthreads();
    if (t < 64) g_ik[s*128 + 64 + t] = ckv_s[64 + t] * s_inv * knorm[t];
    else if (t < 96) {
        int i = t - 64;
        float x0 = ckv_s[2*i], x1 = ckv_s[2*i + 1];
        g_ik[s*128 + i]      = x0*cosb[s*64 + i]      - x1*sinb[s*64 + i];
        g_ik[s*128 + 32 + i] = x1*cosb[s*64 + 32 + i] + x0*sinb[s*64 + 32 + i];
    }
    for (int idx = t; idx < 576; idx += 256)
        g_kv[s*576 + idx] = (idx < 512) ? kp[s*512 + idx] : kr[s*64 + idx - 512];
    for (int idx = t; idx < 1024; idx += 256) {
        int h = idx >> 6, i = idx & 63;
        g_q[s*9216 + h*576 + 512 + i] = qr[(h*2048 + s)*64 + i];
    }
    for (int idx = t; idx < 512; idx += 256) {
        int h = idx >> 5, i = idx & 31;
        int base = s*2048 + h*128;
        float x0 = g_ql[base + 2*i], x1 = g_ql[base + 2*i + 1];
        g_iq[base + i]      = x0*cosb[s*64 + i]      - x1*sinb[s*64 + i];
        g_iq[base + 32 + i] = x1*cosb[s*64 + 32 + i] + x0*sinb[s*64 + 32 + i];
        g_iq[base + 64 + i] = g_ql[base + 64 + i];
        g_iq[base + 96 + i] = g_ql[base + 96 + i];
    }
}

// scores + exact top-1024 (ties -> lowest index, matching jax.lax.top_k)
__global__ __launch_bounds__(256)
void indexer_kernel()
{
    const int qi = blockIdx.x, t = threadIdx.x;
    if (qi < NTOP) {
        for (int k = t; k <= qi; k += 256) g_sel[qi*NTOP + k] = k;
        if (t == 0) g_nsel[qi] = qi + 1;
        return;
    }
    __shared__ float4 iq4[16*33];
    __shared__ float4 ik4[32*33];
    __shared__ float  ssc[SEQ];
    __shared__ float  wsh[16];
    __shared__ unsigned int hist[256];
    __shared__ unsigned long long s_prefix;
    __shared__ unsigned int s_kneed, s_cnt;

    const float4* iqg = (const float4*)g_iq + qi * 512;
#pragma unroll
    for (int u = 0; u < 2; u++) {
        int f = t + 256*u;
        iq4[(f >> 5)*33 + (f & 31)] = iqg[f];
    }
    if (t < 16) wsh[t] = g_w[qi*16 + t];
    if (t == 0) { s_prefix = 0ULL; s_kneed = NTOP; s_cnt = 0; }
    __syncthreads();

    const int n = qi + 1;
    const int row = t >> 3, cb = t & 7;
    for (int k0 = 0; k0 < n; k0 += 32) {
        int k = k0 + row;
        float4* dst = &ik4[row*33];
        if (k < n) {
            const float4* src = (const float4*)g_ik + k*32;
#pragma unroll
            for (int u = 0; u < 4; u++) dst[cb + 8*u] = src[cb + 8*u];
        } else {
            float4 z = make_float4(0.f,0.f,0.f,0.f);
#pragma unroll
            for (int u = 0; u < 4; u++) dst[cb + 8*u] = z;
        }
        __syncthreads();
        const u64* ap0 = (const u64*)&iq4[(cb*2)*33];
        const u64* ap1 = (const u64*)&iq4[(cb*2 + 1)*33];
        const u64* bp  = (const u64*)&ik4[row*33];
        u64 a0a=0ULL, a0b=0ULL, a1a=0ULL, a1b=0ULL;
#pragma unroll
        for (int dc = 0; dc < 32; dc++) {
            u64 b0 = bp[2*dc], b1 = bp[2*dc+1];
            a0a = fma2(ap0[2*dc],   b0, a0a);
            a0b = fma2(ap0[2*dc+1], b1, a0b);
            a1a = fma2(ap1[2*dc],   b0, a1a);
            a1b = fma2(ap1[2*dc+1], b1, a1b);
        }
        float a0 = hsum2(a0a) + hsum2(a0b);
        float a1 = hsum2(a1a) + hsum2(a1b);
        float part = wsh[cb*2]*fmaxf(a0*SCALE, 0.f) + wsh[cb*2+1]*fmaxf(a1*SCALE, 0.f);
        part += __shfl_xor_sync(0xffffffffu, part, 1);
        part += __shfl_xor_sync(0xffffffffu, part, 2);
        part += __shfl_xor_sync(0xffffffffu, part, 4);
        if (cb == 0 && k < n) ssc[k] = part;
        __syncthreads();
    }

    for (int pass = 5; pass >= 0; pass--) {
        const int shift = pass * 8;
        hist[t] = 0u;
        __syncthreads();
        unsigned long long pref = s_prefix;
        for (int k = t; k < n; k += 256) {
            unsigned long long key =
                (((unsigned long long)__float_as_uint(ssc[k])) << 11) | (unsigned)(2047 - k);
            if ((key >> (shift + 8)) == (pref >> (shift + 8)))
                atomicAdd(&hist[(unsigned)(key >> shift) & 255u], 1u);
        }
        __syncthreads();
        if (t == 0) {
            unsigned c = 0;
            for (int d = 255; d >= 0; d--) {
                unsigned c2 = c + hist[d];
                if (c2 >= s_kneed) {
                    s_prefix |= ((unsigned long long)d) << shift;
                    s_kneed  -= c;
                    break;
                }
                c = c2;
            }
        }
        __syncthreads();
    }
    const unsigned long long T = s_prefix;
    for (int k = t; k < n; k += 256) {
        unsigned long long key =
            (((unsigned long long)__float_as_uint(ssc[k])) << 11) | (unsigned)(2047 - k);
        if (key >= T) g_sel[qi*NTOP + atomicAdd(&s_cnt, 1u)] = k;
    }
    if (t == 0) g_nsel[qi] = NTOP;
}

// sparse attention v1: block/query, 8 warps x 2 heads, online softmax, f32x2
#define KTILE 16
__global__ __launch_bounds__(256, 2)
void attn_kernel()
{
    __shared__ float4 kvs[KTILE * 144];
    const int qi = blockIdx.x, t = threadIdx.x;
    const int w = t >> 5, lane = t & 31;
    const int h0 = w*2, h1 = h0 + 1;
    const bool half = lane < 16;

    const u64* q2 = (const u64*)g_q + (long long)qi * (NH*DQK/2);
    u64 qa[10], qb[10];
#pragma unroll
    for (int u = 0; u < 4; u++) {
        qa[2*u]   = q2[h0*288 + (lane+32*u)*2];
        qa[2*u+1] = q2[h0*288 + (lane+32*u)*2 + 1];
        qb[2*u]   = q2[h1*288 + (lane+32*u)*2];
        qb[2*u+1] = q2[h1*288 + (lane+32*u)*2 + 1];
    }
    qa[8]=qa[9]=qb[8]=qb[9]=0ULL;
    if (half) {
        qa[8] = q2[h0*288 + (128+lane)*2]; qa[9] = q2[h0*288 + (128+lane)*2 + 1];
        qb[8] = q2[h1*288 + (128+lane)*2]; qb[9] = q2[h1*288 + (128+lane)*2 + 1];
    }

    float m0 = -1e30f, l0 = 0.f, m1 = -1e30f, l1 = 0.f;
    u64 o0[8], o1[8];
#pragma unroll
    for (int p = 0; p < 8; p++) { o0[p] = 0ULL; o1[p] = 0ULL; }

    const int n = g_nsel[qi];
    const int* lst = g_sel + qi*NTOP;

    for (int base = 0; base < n; base += KTILE) {
        int tk = n - base; if (tk > KTILE) tk = KTILE;
#pragma unroll
        for (int rr = 0; rr < 2; rr++) {
            int r = w*2 + rr;
            if (r < tk) {
                int key = __ldg(&lst[base + r]);
                const float4* src = (const float4*)g_kv + key*144;
                float4* dst = kvs + r*144;
                dst[lane]      = src[lane];
                dst[lane + 32] = src[lane + 32];
                dst[lane + 64] = src[lane + 64];
                dst[lane + 96] = src[lane + 96];
                if (half) dst[128 + lane] = src[128 + lane];
            }
        }
        __syncthreads();
#pragma unroll 2
        for (int j = 0; j < tk; j++) {
            const u64* kr = (const u64*)(kvs + j*144);
            u64 b[8];
#pragma unroll
            for (int u = 0; u < 4; u++) {
                b[2*u]   = kr[(lane+32*u)*2];
                b[2*u+1] = kr[(lane+32*u)*2 + 1];
            }
            u64 sa2 = 0ULL, sb2 = 0ULL;
#pragma unroll
            for (int p = 0; p < 8; p++) {
                sa2 = fma2(qa[p], b[p], sa2);
                sb2 = fma2(qb[p], b[p], sb2);
            }
            if (half) {
                u64 bt0 = kr[(128+lane)*2], bt1 = kr[(128+lane)*2 + 1];
                sa2 = fma2(qa[8], bt0, sa2); sa2 = fma2(qa[9], bt1, sa2);
                sb2 = fma2(qb[8], bt0, sb2); sb2 = fma2(qb[9], bt1, sb2);
            }
            float sA = hsum2(sa2), sB = hsum2(sb2);
#pragma unroll
            for (int o = 16; o; o >>= 1) {
                sA += __shfl_xor_sync(0xffffffffu, sA, o);
                sB += __shfl_xor_sync(0xffffffffu, sB, o);
            }
            float lg0 = sA * SCALE, lg1 = sB * SCALE;
            if (lg0 > m0) {
                float c = __expf(m0 - lg0); l0 *= c;
                u64 c2 = pkdup(c);
#pragma unroll
                for (int p = 0; p < 8; p++) o0[p] = mul2(o0[p], c2);
                m0 = lg0;
            }
            float p0 = __expf(lg0 - m0); l0 += p0;
            u64 p02 = pkdup(p0);
#pragma unroll
            for (int p = 0; p < 8; p++) o0[p] = fma2(p02, b[p], o0[p]);
            if (lg1 > m1) {
                float c = __expf(m1 - lg1); l1 *= c;
                u64 c2 = pkdup(c);
#pragma unroll
                for (int p = 0; p < 8; p++) o1[p] = mul2(o1[p], c2);
                m1 = lg1;
            }
            float p1 = __expf(lg1 - m1); l1 += p1;
            u64 p12 = pkdup(p1);
#pragma unroll
            for (int p = 0; p < 8; p++) o1[p] = fma2(p12, b[p], o1[p]);
        }
        __syncthreads();
    }
    u64 i02 = pkdup(1.f/l0), i12 = pkdup(1.f/l1);
    float4* ao = (float4*)g_attn + (long long)qi * (NH*DV/4);
#pragma unroll
    for (int u = 0; u < 4; u++) {
        float4 v, v2;
        u64 r0 = mul2(o0[2*u], i02), r1 = mul2(o0[2*u+1], i02);
        upk(r0, v.x, v.y); upk(r1, v.z, v.w);
        ao[h0*128 + lane + 32*u] = v;
        u64 s0 = mul2(o1[2*u], i12), s1 = mul2(o1[2*u+1], i12);
        upk(s0, v2.x, v2.y); upk(s1, v2.z, v2.w);
        ao[h1*128 + lane + 32*u] = v2;
    }
}

template <typename T> static T* sym(const void* s) {
    void* p = nullptr; cudaGetSymbolAddress(&p, s); return (T*)p;
}

extern "C" void kernel_launch(void* const* d_in, const int* in_sizes, int n_in,
                              void* d_out, int out_size)
{
    (void)in_sizes; (void)n_in; (void)out_size;
    const float* q_latent = (const float*)d_in[0];
    const float* hidden   = (const float*)d_in[1];
    const float* cosb     = (const float*)d_in[2];
    const float* sinb     = (const float*)d_in[3];
    const float* q_pass   = (const float*)d_in[4];
    const float* q_rot    = (const float*)d_in[5];
    const float* k_pass   = (const float*)d_in[6];
    const float* k_rot    = (const float*)d_in[7];
    const float* kvb      = (const float*)d_in[9];
    const float* wqb      = (const float*)d_in[10];
    const float* wkw      = (const float*)d_in[11];
    const float* knorm    = (const float*)d_in[12];
    const float* wpw      = (const float*)d_in[13];
    const float* wpb      = (const float*)d_in[14];
    float* out = (float*)d_out;

    float* p_attn = sym<float>(g_attn);

    // 1: all dense projections in one 1536-block launch
    sgemm_all<<<1536, 256>>>(q_latent, wqb, hidden, wkw, wpw, q_pass, kvb);
    // 2: fused reductions + builds + ropes
    fused_build<<<SEQ, 256>>>(k_pass, k_rot, q_rot, cosb, sinb, knorm, wpb);
    // 3: indexer scores + exact top-1024
    indexer_kernel<<<SEQ, 256>>>();
    // 4: sparse attention  (<- profiled slot next round)
    attn_kernel<<<SEQ, 256>>>();
    // 5: out[s,h,d] = sum_r attn[s,h,r] * v_b[h,d,r]
    sgemm_nt<<<dim3(1,16,16), 256>>>(p_attn, kvb + 128*512, out, 128, 512,
                                     NH*DV, 512, NH*128,
                                     512LL, 256LL*512, 128LL, 0);
}